// round 14
// baseline (speedup 1.0000x reference)
#include <cuda_runtime.h>

#define NB 8
#define CC 64
#define TT 256
#define VQ 90
#define VK 50
#define SS 4
#define LAG 4
#define NLAG (LAG + 1)
#define TQ (TT - LAG)                 // 252
#define COLS_Q (TQ * VQ)              // 22680
#define COLS_T (TT * VQ)              // 23040
#define COLS_K (TT * VK)              // 12800
#define BN_EPS 1e-5f

// ---------------- tf32 mma helpers ----------------
__device__ __forceinline__ unsigned f2tf32(float x) {
    unsigned r;
    asm("cvt.rna.tf32.f32 %0, %1;" : "=r"(r) : "f"(x));
    return r;
}
__device__ __forceinline__ void mma_tf32(
    float& c0, float& c1, float& c2, float& c3,
    unsigned a0, unsigned a1, unsigned a2, unsigned a3,
    unsigned b0, unsigned b1)
{
    asm("mma.sync.aligned.m16n8k8.row.col.f32.tf32.tf32.f32 "
        "{%0,%1,%2,%3},{%4,%5,%6,%7},{%8,%9},{%0,%1,%2,%3};"
        : "+f"(c0), "+f"(c1), "+f"(c2), "+f"(c3)
        : "r"(a0), "r"(a1), "r"(a2), "r"(a3), "r"(b0), "r"(b1));
}

// ---------------- scratch (static device memory; no allocations) ----------------
__device__ float g_kq  [NB * SS * CC * COLS_K];   // kq[n][s*64+c'][t*VK+vk] = (M_s x_k + bkq)
__device__ float g_vw  [NB * SS * CC * COLS_K];   // vw[n][s*64+co][t*VK+vk] = (Mv x_v + bv2)
__device__ float g_o1  [NB * CC * COLS_T];
__device__ float g_d   [NB * CC * COLS_T];
__device__ float g_att5[NLAG * NB * SS * VQ * VK];
__device__ float g_att [NB * SS * VQ * VK];
__device__ float g_stats[2 * CC * 2];
__device__ float g_statsacc[2 * CC * 2];
__device__ float g_M   [SS * CC * CC];            // fused Wq^T Wk
__device__ float g_Mv  [SS * CC * CC];            // fused Wout_s Wv
__device__ float g_bkq [SS * CC];
__device__ float g_u   [SS * CC];                 // bq^T Wk
__device__ float g_bv2 [SS * CC];
__device__ float g_beta[SS];                      // bq^T bk
__device__ float g_corr[NB * SS * NLAG * VK];

// ---------------- zero kernel ----------------
__global__ void zero_kernel(float* p, int n) {
    int i = blockIdx.x * blockDim.x + threadIdx.x;
    if (i < n) p[i] = 0.f;
}

// ---------------- tiny weight precontractions (fp32) ----------------
__global__ void precompute_kernel(
    const float* __restrict__ Wq, const float* __restrict__ bq,
    const float* __restrict__ Wk, const float* __restrict__ bk,
    const float* __restrict__ Wv, const float* __restrict__ bv,
    const float* __restrict__ Wout,
    float* __restrict__ M, float* __restrict__ Mv, float* __restrict__ bkq,
    float* __restrict__ u, float* __restrict__ bv2, float* __restrict__ beta)
{
    int idx = blockIdx.x * 256 + threadIdx.x;
    if (idx < 16384) {                 // M[s][c'][c'']
        int s = idx >> 12, cp = (idx >> 6) & 63, cpp = idx & 63;
        float acc = 0.f;
        for (int c = 0; c < 64; c++)
            acc += Wq[((s << 6) + c) * 64 + cp] * Wk[((s << 6) + c) * 64 + cpp];
        M[idx] = acc;
    } else if (idx < 32768) {          // Mv[(s,co)][c'']
        int j = idx - 16384;
        int sco = j >> 6, cpp = j & 63;
        int s = sco >> 6, co = sco & 63;
        float acc = 0.f;
        for (int c = 0; c < 64; c++)
            acc += Wout[co * 256 + (s << 6) + c] * Wv[c * 64 + cpp];
        Mv[j] = acc;
    } else if (idx < 33024) {          // bkq[(s,c')]
        int j = idx - 32768; int s = j >> 6, cp = j & 63;
        float acc = 0.f;
        for (int c = 0; c < 64; c++)
            acc += Wq[((s << 6) + c) * 64 + cp] * bk[(s << 6) + c];
        bkq[j] = acc;
    } else if (idx < 33280) {          // u[(s,c'')]
        int j = idx - 33024; int s = j >> 6, cpp = j & 63;
        float acc = 0.f;
        for (int c = 0; c < 64; c++)
            acc += bq[(s << 6) + c] * Wk[((s << 6) + c) * 64 + cpp];
        u[j] = acc;
    } else if (idx < 33536) {          // bv2[(s,co)]
        int j = idx - 33280; int s = j >> 6, co = j & 63;
        float acc = 0.f;
        for (int c = 0; c < 64; c++)
            acc += Wout[co * 256 + (s << 6) + c] * bv[c];
        bv2[j] = acc;
    } else if (idx < 33540) {          // beta[s]
        int s = idx - 33536;
        float acc = 0.f;
        for (int c = 0; c < 64; c++)
            acc += bq[(s << 6) + c] * bk[(s << 6) + c];
        beta[s] = acc;
    }
}

// ---------------- conv1x1 GEMM via tf32 mma ----------------
// O[n][row0+r][col] = sum_k W[(row0+r)*lda + k] X[n][k][col] (+ bias[row])
// Block tile: 64 rows x 256 cols, K-chunk 32. 8 warps (2M x 4N), warp tile 32x64.
// statsAcc != nullptr: fused per-row (channel) sum/sumsq accumulation.
__global__ __launch_bounds__(256) void gemm_tf32(
    const float* __restrict__ W, const float* __restrict__ bias,
    const float* __restrict__ X, float* __restrict__ O,
    int K, int cols, int rsB, long bsB, long bsC, int lda,
    float* __restrict__ statsAcc)
{
    __shared__ __align__(16) unsigned char gsm[43008];
    unsigned (*Ws)[36]  = reinterpret_cast<unsigned (*)[36]>(gsm);
    unsigned (*Xs)[264] = reinterpret_cast<unsigned (*)[264]>(gsm + 9216);
    float    (*Cs)[260] = reinterpret_cast<float (*)[260]>(gsm);
    __shared__ float rsum[64], rsq[64];

    int tid = threadIdx.x;
    int lane = tid & 31;
    int w = tid >> 5;
    int wm = w & 1, wn = w >> 1;
    int lr = lane >> 2, lc = lane & 3;
    int n = blockIdx.z;
    int row0 = blockIdx.y * 64;
    int col0 = blockIdx.x * 256;
    const float* Xn = X + (long)n * bsB;
    float* On = O + (long)n * bsC;

    if (statsAcc && tid < 64) { rsum[tid] = 0.f; rsq[tid] = 0.f; }

    float acc[2][8][4];
#pragma unroll
    for (int mt = 0; mt < 2; mt++)
#pragma unroll
        for (int nt = 0; nt < 8; nt++)
#pragma unroll
            for (int e = 0; e < 4; e++) acc[mt][nt][e] = 0.f;

    for (int kc = 0; kc < K; kc += 32) {
        __syncthreads();
#pragma unroll
        for (int it = 0; it < 2; it++) {
            int idx = tid + it * 256;
            int r = idx >> 3, q4 = idx & 7;
            float4 wv = *reinterpret_cast<const float4*>(
                &W[(long)(row0 + r) * lda + kc + q4 * 4]);
            Ws[r][q4 * 4 + 0] = f2tf32(wv.x);
            Ws[r][q4 * 4 + 1] = f2tf32(wv.y);
            Ws[r][q4 * 4 + 2] = f2tf32(wv.z);
            Ws[r][q4 * 4 + 3] = f2tf32(wv.w);
        }
#pragma unroll
        for (int it = 0; it < 8; it++) {
            int idx = tid + it * 256;
            int kk = idx >> 6, c4 = idx & 63;
            int col = col0 + c4 * 4;
            float4 xv = make_float4(0.f, 0.f, 0.f, 0.f);
            if (col < cols)
                xv = *reinterpret_cast<const float4*>(&Xn[(long)(kc + kk) * rsB + col]);
            Xs[kk][c4 * 4 + 0] = f2tf32(xv.x);
            Xs[kk][c4 * 4 + 1] = f2tf32(xv.y);
            Xs[kk][c4 * 4 + 2] = f2tf32(xv.z);
            Xs[kk][c4 * 4 + 3] = f2tf32(xv.w);
        }
        __syncthreads();
#pragma unroll
        for (int kk = 0; kk < 32; kk += 8) {
            unsigned a[2][4];
#pragma unroll
            for (int mt = 0; mt < 2; mt++) {
                int m0 = wm * 32 + mt * 16;
                a[mt][0] = Ws[m0 + lr][kk + lc];
                a[mt][1] = Ws[m0 + 8 + lr][kk + lc];
                a[mt][2] = Ws[m0 + lr][kk + 4 + lc];
                a[mt][3] = Ws[m0 + 8 + lr][kk + 4 + lc];
            }
            unsigned b[8][2];
#pragma unroll
            for (int nt = 0; nt < 8; nt++) {
                int n0 = wn * 64 + nt * 8;
                b[nt][0] = Xs[kk + lc][n0 + lr];
                b[nt][1] = Xs[kk + 4 + lc][n0 + lr];
            }
#pragma unroll
            for (int mt = 0; mt < 2; mt++)
#pragma unroll
                for (int nt = 0; nt < 8; nt++)
                    mma_tf32(acc[mt][nt][0], acc[mt][nt][1], acc[mt][nt][2], acc[mt][nt][3],
                             a[mt][0], a[mt][1], a[mt][2], a[mt][3],
                             b[nt][0], b[nt][1]);
        }
    }
    for (int h = 0; h < 2; h++) {
        __syncthreads();
        if (wm == h) {
#pragma unroll
            for (int mt = 0; mt < 2; mt++) {
                int rloc = mt * 16 + lr;
                int r = row0 + h * 32 + rloc;
                float bv0 = bias ? bias[r] : 0.f;
                float bv8 = bias ? bias[r + 8] : 0.f;
#pragma unroll
                for (int nt = 0; nt < 8; nt++) {
                    int c = wn * 64 + nt * 8 + lc * 2;
                    Cs[rloc][c]         = acc[mt][nt][0] + bv0;
                    Cs[rloc][c + 1]     = acc[mt][nt][1] + bv0;
                    Cs[rloc + 8][c]     = acc[mt][nt][2] + bv8;
                    Cs[rloc + 8][c + 1] = acc[mt][nt][3] + bv8;
                }
            }
        }
        __syncthreads();
#pragma unroll
        for (int it = 0; it < 8; it++) {
            int idx = tid + it * 256;
            int rr = idx >> 6, c4 = idx & 63;
            int col = col0 + c4 * 4;
            if (col < cols) {
                float4 val = *reinterpret_cast<const float4*>(&Cs[rr][c4 * 4]);
                *reinterpret_cast<float4*>(
                    &On[(long)(row0 + h * 32 + rr) * cols + col]) = val;
            }
        }
        if (statsAcc) {
            int rr = tid & 31, seg = tid >> 5;
            float s = 0.f, q2 = 0.f;
#pragma unroll
            for (int j = 0; j < 32; j++) {
                int col = col0 + seg * 32 + j;
                if (col < cols) {
                    float xv = Cs[rr][seg * 32 + j];
                    s += xv; q2 += xv * xv;
                }
            }
            atomicAdd(&rsum[h * 32 + rr], s);
            atomicAdd(&rsq[h * 32 + rr], q2);
        }
    }
    if (statsAcc) {
        __syncthreads();
        if (tid < 64) {
            atomicAdd(&statsAcc[(row0 + tid) * 2 + 0], rsum[tid]);
            atomicAdd(&statsAcc[(row0 + tid) * 2 + 1], rsq[tid]);
        }
    }
}

// ---------------- bias cross-term: corr[n,s,l,vk] = sum_t (u_s . x_k)[t+l,vk] window + Tq*beta[s] ----------------
__global__ __launch_bounds__(256) void corr_kernel(
    const float* __restrict__ xk, const float* __restrict__ u,
    const float* __restrict__ beta, float* __restrict__ corr)
{
    __shared__ float w[64][52];
    int tid = threadIdx.x;
    int n = blockIdx.x >> 2, s = blockIdx.x & 3;
    const float* us = u + s * CC;
    float acc[NLAG] = {0.f, 0.f, 0.f, 0.f, 0.f};

    for (int t0 = 0; t0 < TT; t0 += 64) {
        for (int i = tid; i < 64 * 52; i += 256) (&w[0][0])[i] = 0.f;
        __syncthreads();
        for (int c = 0; c < CC; c++) {
            float uv = us[c];
            const float* xb = xk + ((long)n * CC + c) * COLS_K + t0 * VK;
            for (int i = tid; i < 64 * VK; i += 256) {
                int r = i / VK, vk = i - r * VK;
                w[r][vk] += uv * xb[i];
            }
        }
        __syncthreads();
        if (tid < VK) {
            for (int tt = 0; tt < 64; tt++) {
                int t = t0 + tt;
                float val = w[tt][tid];
                int lo = t - (TQ - 1); if (lo < 0) lo = 0;
                int hi = t < LAG ? t : LAG;
                for (int l = lo; l <= hi; l++) acc[l] += val;
            }
        }
        __syncthreads();
    }
    if (tid < VK) {
        float b = (float)TQ * beta[s];
        for (int l = 0; l <= LAG; l++)
            corr[(((long)n * SS + s) * NLAG + l) * VK + tid] = acc[l] + b;
    }
}

// ---------------- 5-lag attention scores via tf32 mma, software-pipelined ----------------
// A = x_q[n, c-chunk, t<TQ, vq] (stride COLS_T), B = kq[n, s, c-chunk, t+l, vk].
#define SC_NQ 13                     // ceil(64*90 / 448)
#define SC_NK 8                      // ceil(68*50 / 448)
__global__ __launch_bounds__(448) void scores_tf32(
    const float* __restrict__ xq, const float* __restrict__ kq,
    float* __restrict__ att5)
{
    __shared__ unsigned q_s[64][104];  // [t][vq pad 90->104]
    __shared__ unsigned k_s[68][56];   // [t (+4 halo)][vk pad 50->56]
    int tid = threadIdx.x;
    int lane = tid & 31;
    int w = tid >> 5;                  // 0..13
    int wm = w & 1, wn = w >> 1;       // wn 0..6
    int lr = lane >> 2, lc = lane & 3;
    int ns = blockIdx.x;
    int n = ns >> 2, s = ns & 3;
    int c0 = blockIdx.y * 4;

    const float* qbase = xq + (long)(n * CC + c0) * COLS_T;
    const float* kbase = kq + (long)(n * SS * CC + s * CC + c0) * COLS_K;

    int lagv[5], vkbv[5];
#pragma unroll
    for (int nt = 0; nt < 5; nt++) {
        int nn = wn * 40 + nt * 8;
        lagv[nt] = nn / 56;
        vkbv[nt] = nn % 56 + lr;
    }

    float acc[3][5][4];
#pragma unroll
    for (int mt = 0; mt < 3; mt++)
#pragma unroll
        for (int nt = 0; nt < 5; nt++)
#pragma unroll
            for (int e = 0; e < 4; e++) acc[mt][nt][e] = 0.f;

    for (int idx = tid; idx < 64 * 104; idx += 448) (&q_s[0][0])[idx] = 0u;
    for (int idx = tid; idx < 68 * 56; idx += 448) (&k_s[0][0])[idx] = 0u;

    float qv[SC_NQ], kv[SC_NK];
    {
        const float* qr = qbase;
        const float* kr = kbase;
#pragma unroll
        for (int i = 0; i < SC_NQ; i++) {
            int idx = tid + i * 448;
            qv[i] = (idx < 64 * VQ) ? qr[idx] : 0.f;
        }
#pragma unroll
        for (int i = 0; i < SC_NK; i++) {
            int idx = tid + i * 448;
            kv[i] = (idx < 68 * VK) ? kr[idx] : 0.f;
        }
    }
    __syncthreads();
#pragma unroll
    for (int i = 0; i < SC_NQ; i++) {
        int idx = tid + i * 448;
        if (idx < 64 * VQ) { int r = idx / VQ, c = idx - r * VQ; q_s[r][c] = f2tf32(qv[i]); }
    }
#pragma unroll
    for (int i = 0; i < SC_NK; i++) {
        int idx = tid + i * 448;
        if (idx < 68 * VK) { int r = idx / VK, c = idx - r * VK; k_s[r][c] = f2tf32(kv[i]); }
    }

#pragma unroll 1
    for (int chunk = 0; chunk < 16; chunk++) {
        __syncthreads();
        int nxt = chunk + 1;
        if (nxt < 16) {
            int cc = nxt >> 2, tch = nxt & 3;
            int t0 = tch * 64;
            const float* qr = qbase + (long)cc * COLS_T + (long)t0 * VQ;
            int qlim = (TQ - t0) * VQ; if (qlim > 64 * VQ) qlim = 64 * VQ;
            const float* kr = kbase + (long)cc * COLS_K + (long)t0 * VK;
            int klim = (TT - t0) * VK; if (klim > 68 * VK) klim = 68 * VK;
#pragma unroll
            for (int i = 0; i < SC_NQ; i++) {
                int idx = tid + i * 448;
                qv[i] = (idx < qlim) ? qr[idx] : 0.f;
            }
#pragma unroll
            for (int i = 0; i < SC_NK; i++) {
                int idx = tid + i * 448;
                kv[i] = (idx < klim) ? kr[idx] : 0.f;
            }
        }
#pragma unroll
        for (int kk = 0; kk < 64; kk += 8) {
            unsigned a[3][4];
#pragma unroll
            for (int mt = 0; mt < 3; mt++) {
                int m0 = wm * 48 + mt * 16;
                a[mt][0] = q_s[kk + lc][m0 + lr];
                a[mt][1] = q_s[kk + lc][m0 + 8 + lr];
                a[mt][2] = q_s[kk + 4 + lc][m0 + lr];
                a[mt][3] = q_s[kk + 4 + lc][m0 + 8 + lr];
            }
            unsigned b[5][2];
#pragma unroll
            for (int nt = 0; nt < 5; nt++) {
                b[nt][0] = k_s[kk + lc + lagv[nt]][vkbv[nt]];
                b[nt][1] = k_s[kk + 4 + lc + lagv[nt]][vkbv[nt]];
            }
#pragma unroll
            for (int mt = 0; mt < 3; mt++)
#pragma unroll
                for (int nt = 0; nt < 5; nt++)
                    mma_tf32(acc[mt][nt][0], acc[mt][nt][1], acc[mt][nt][2], acc[mt][nt][3],
                             a[mt][0], a[mt][1], a[mt][2], a[mt][3],
                             b[nt][0], b[nt][1]);
        }
        __syncthreads();
        if (nxt < 16) {
#pragma unroll
            for (int i = 0; i < SC_NQ; i++) {
                int idx = tid + i * 448;
                if (idx < 64 * VQ) { int r = idx / VQ, c = idx - r * VQ; q_s[r][c] = f2tf32(qv[i]); }
            }
#pragma unroll
            for (int i = 0; i < SC_NK; i++) {
                int idx = tid + i * 448;
                if (idx < 68 * VK) { int r = idx / VK, c = idx - r * VK; k_s[r][c] = f2tf32(kv[i]); }
            }
        }
    }

#pragma unroll
    for (int mt = 0; mt < 3; mt++) {
        int vq = wm * 48 + mt * 16 + lr;
#pragma unroll
        for (int nt = 0; nt < 5; nt++) {
            int nn = wn * 40 + nt * 8 + lc * 2;
            int l = nn / 56;
            int vk = nn % 56;
            long base = (((long)(l * NB + n) * SS + s) * VQ);
            if (vq < VQ) {
                if (vk < VK)     atomicAdd(&att5[(base + vq) * VK + vk], acc[mt][nt][0]);
                if (vk + 1 < VK) atomicAdd(&att5[(base + vq) * VK + vk + 1], acc[mt][nt][1]);
            }
            if (vq + 8 < VQ) {
                if (vk < VK)     atomicAdd(&att5[(base + vq + 8) * VK + vk], acc[mt][nt][2]);
                if (vk + 1 < VK) atomicAdd(&att5[(base + vq + 8) * VK + vk + 1], acc[mt][nt][3]);
            }
        }
    }
}

// ---------------- (max+mean)/2 over lags (+bias corr), /scale, softmax over vk ----------------
__global__ void softmax_kernel(const float* __restrict__ att5,
                               const float* __restrict__ corr,
                               float* __restrict__ att)
{
    int r = blockIdx.x;               // (n*S+s)*VQ+vq, 2880 rows
    int tid = threadIdx.x;            // 64
    __shared__ float red[64];
    const float halfInv = 0.5f / sqrtf((float)(CC * TQ));
    int nsIdx = r / VQ;               // n*SS+s
    float p = -1e30f;
    if (tid < VK) {
        float mx = -1e30f, sm = 0.f;
#pragma unroll
        for (int l = 0; l < NLAG; l++) {
            float v = att5[((long)l * (NB * SS * VQ) + r) * VK + tid]
                    + corr[((long)nsIdx * NLAG + l) * VK + tid];
            mx = fmaxf(mx, v);
            sm += v;
        }
        p = (mx + sm * 0.2f) * halfInv;
    }
    red[tid] = p;
    __syncthreads();
    for (int o = 32; o > 0; o >>= 1) {
        if (tid < o) red[tid] = fmaxf(red[tid], red[tid + o]);
        __syncthreads();
    }
    float m = red[0];
    __syncthreads();
    float e = (tid < VK) ? expf(p - m) : 0.f;
    red[tid] = e;
    __syncthreads();
    for (int o = 32; o > 0; o >>= 1) {
        if (tid < o) red[tid] += red[tid + o];
        __syncthreads();
    }
    if (tid < VK) att[(long)r * VK + tid] = e / red[0];
}

// ---------------- o1[n,co,t,vq] = bout[co] + sum_{s,vk} vw[n,s,co,t,vk] * att[n,s,vq,vk] ----------------
__global__ __launch_bounds__(256) void att_out_tf32(
    const float* __restrict__ att, const float* __restrict__ vw,
    const float* __restrict__ bout, float* __restrict__ o1,
    float* __restrict__ statsAcc)
{
    __shared__ __align__(16) unsigned char ysm[38656];
    unsigned (*vt_s)[60]  = reinterpret_cast<unsigned (*)[60]>(ysm);
    unsigned (*at_s)[104] = reinterpret_cast<unsigned (*)[104]>(ysm + 15360);
    float    (*Cs)[96]    = reinterpret_cast<float (*)[96]>(ysm);
    __shared__ float r1[8], r2[8];

    int tid = threadIdx.x;
    int lane = tid & 31;
    int w = tid >> 5;
    int wm = w & 1, wn = w >> 1;
    int lr = lane >> 2, lc = lane & 3;
    int n = blockIdx.y;
    int ct0 = blockIdx.x * 64;
    int co = ct0 >> 8;
    int t0 = ct0 & 255;

    for (int idx = tid; idx < 64 * 60; idx += 256) (&vt_s[0][0])[idx] = 0u;
    for (int idx = tid; idx < 56 * 104; idx += 256) (&at_s[0][0])[idx] = 0u;

    float acc[2][3][4];
#pragma unroll
    for (int mt = 0; mt < 2; mt++)
#pragma unroll
        for (int nt = 0; nt < 3; nt++)
#pragma unroll
            for (int e = 0; e < 4; e++) acc[mt][nt][e] = 0.f;

#pragma unroll 1
    for (int s = 0; s < SS; s++) {
        __syncthreads();
        const float* ab = att + (long)(n * SS + s) * (VQ * VK);
        for (int idx = tid; idx < VQ * VK; idx += 256) {
            int vq = idx / VK, vk = idx - vq * VK;
            at_s[vk][vq] = f2tf32(ab[idx]);
        }
        const float* vb = vw + ((long)(n * SS + s) * CC + co) * COLS_K + (long)t0 * VK;
        for (int idx = tid; idx < 64 * VK; idx += 256) {
            int r = idx / VK, c = idx - r * VK;
            vt_s[r][c] = f2tf32(vb[idx]);
        }
        __syncthreads();
#pragma unroll
        for (int kk = 0; kk < 56; kk += 8) {
            unsigned a[2][4];
#pragma unroll
            for (int mt = 0; mt < 2; mt++) {
                int m0 = wm * 32 + mt * 16;
                a[mt][0] = vt_s[m0 + lr][kk + lc];
                a[mt][1] = vt_s[m0 + 8 + lr][kk + lc];
                a[mt][2] = vt_s[m0 + lr][kk + 4 + lc];
                a[mt][3] = vt_s[m0 + 8 + lr][kk + 4 + lc];
            }
            unsigned b[3][2];
#pragma unroll
            for (int nt = 0; nt < 3; nt++) {
                int n0 = wn * 24 + nt * 8;
                b[nt][0] = at_s[kk + lc][n0 + lr];
                b[nt][1] = at_s[kk + 4 + lc][n0 + lr];
            }
#pragma unroll
            for (int mt = 0; mt < 2; mt++)
#pragma unroll
                for (int nt = 0; nt < 3; nt++)
                    mma_tf32(acc[mt][nt][0], acc[mt][nt][1], acc[mt][nt][2], acc[mt][nt][3],
                             a[mt][0], a[mt][1], a[mt][2], a[mt][3],
                             b[nt][0], b[nt][1]);
        }
    }

    __syncthreads();
    float bv = bout[co];
#pragma unroll
    for (int mt = 0; mt < 2; mt++) {
        int rloc = wm * 32 + mt * 16 + lr;
#pragma unroll
        for (int nt = 0; nt < 3; nt++) {
            int c = wn * 24 + nt * 8 + lc * 2;
            Cs[rloc][c]         = acc[mt][nt][0] + bv;
            Cs[rloc][c + 1]     = acc[mt][nt][1] + bv;
            Cs[rloc + 8][c]     = acc[mt][nt][2] + bv;
            Cs[rloc + 8][c + 1] = acc[mt][nt][3] + bv;
        }
    }
    __syncthreads();
    long obase = (long)n * CC * COLS_T + (long)ct0 * VQ;
    float s1 = 0.f, s2 = 0.f;
#pragma unroll
    for (int it = 0; it < 12; it++) {
        int idx = tid + it * 256;
        if (idx < 64 * 45) {
            int r = idx / 45, c2 = idx - r * 45;
            float2 val = *reinterpret_cast<const float2*>(&Cs[r][c2 * 2]);
            *reinterpret_cast<float2*>(&o1[obase + (long)r * VQ + c2 * 2]) = val;
            s1 += val.x + val.y;
            s2 += val.x * val.x + val.y * val.y;
        }
    }
#pragma unroll
    for (int o = 16; o > 0; o >>= 1) {
        s1 += __shfl_down_sync(0xffffffff, s1, o);
        s2 += __shfl_down_sync(0xffffffff, s2, o);
    }
    if (lane == 0) { r1[w] = s1; r2[w] = s2; }
    __syncthreads();
    if (tid == 0) {
        float t1 = 0.f, t2 = 0.f;
#pragma unroll
        for (int i = 0; i < 8; i++) { t1 += r1[i]; t2 += r2[i]; }
        atomicAdd(&statsAcc[co * 2 + 0], t1);
        atomicAdd(&statsAcc[co * 2 + 1], t2);
    }
}

// ---------------- finalize BN stats from fused accumulators ----------------
__global__ void finalize_stats(const float* __restrict__ acc, float* __restrict__ stats)
{
    int i = threadIdx.x;              // 128 = which*64+co
    float M = (float)NB * COLS_T;
    float mean = acc[i * 2 + 0] / M;
    float var = acc[i * 2 + 1] / M - mean * mean;
    stats[i * 2 + 0] = mean;
    stats[i * 2 + 1] = rsqrtf(var + BN_EPS);
}

// ---------------- BN both paths + add + leaky relu (vectorized) ----------------
__global__ void final_kernel(const float* __restrict__ o1, const float* __restrict__ d,
                             const float* __restrict__ stats,
                             const float* __restrict__ gout, const float* __restrict__ bout,
                             const float* __restrict__ gdown, const float* __restrict__ bdown,
                             float* __restrict__ out)
{
    long i4 = (long)blockIdx.x * blockDim.x + threadIdx.x;
    long total4 = (long)NB * CC * COLS_T / 4;
    if (i4 >= total4) return;
    long idx = i4 * 4;
    int co = (int)((idx / COLS_T) % CC);
    float mo = stats[co * 2 + 0], iso = stats[co * 2 + 1];
    float md = stats[(CC + co) * 2 + 0], isd = stats[(CC + co) * 2 + 1];
    float so = iso * gout[co], sd = isd * gdown[co];
    float bo = bout[co] - mo * so, bd = bdown[co] - md * sd;
    float4 a = *reinterpret_cast<const float4*>(&o1[idx]);
    float4 b = *reinterpret_cast<const float4*>(&d[idx]);
    float4 r;
    float v;
    v = a.x * so + bo + b.x * sd + bd; r.x = v > 0.f ? v : 0.1f * v;
    v = a.y * so + bo + b.y * sd + bd; r.y = v > 0.f ? v : 0.1f * v;
    v = a.z * so + bo + b.z * sd + bd; r.z = v > 0.f ? v : 0.1f * v;
    v = a.w * so + bo + b.w * sd + bd; r.w = v > 0.f ? v : 0.1f * v;
    *reinterpret_cast<float4*>(&out[idx]) = r;
}

// ---------------- launch ----------------
extern "C" void kernel_launch(void* const* d_in, const int* in_sizes, int n_in,
                              void* d_out, int out_size)
{
    const float* x_q   = (const float*)d_in[0];
    const float* x_k   = (const float*)d_in[1];
    const float* x_v   = (const float*)d_in[2];
    const float* Wq    = (const float*)d_in[3];
    const float* bq    = (const float*)d_in[4];
    const float* Wk    = (const float*)d_in[5];
    const float* bk    = (const float*)d_in[6];
    const float* Wv    = (const float*)d_in[7];
    const float* bv    = (const float*)d_in[8];
    const float* Wout  = (const float*)d_in[9];
    const float* bout  = (const float*)d_in[10];
    const float* g_out = (const float*)d_in[11];
    const float* b_out = (const float*)d_in[12];
    const float* Wdown = (const float*)d_in[13];
    const float* bdown = (const float*)d_in[14];
    const float* g_dn  = (const float*)d_in[15];
    const float* b_dn  = (const float*)d_in[16];

    float *kq, *vw, *o1, *db, *att5, *att, *stats, *sacc;
    float *M, *Mv, *bkq, *u, *bv2, *beta, *corr;
    cudaGetSymbolAddress((void**)&kq,    g_kq);
    cudaGetSymbolAddress((void**)&vw,    g_vw);
    cudaGetSymbolAddress((void**)&o1,    g_o1);
    cudaGetSymbolAddress((void**)&db,    g_d);
    cudaGetSymbolAddress((void**)&att5,  g_att5);
    cudaGetSymbolAddress((void**)&att,   g_att);
    cudaGetSymbolAddress((void**)&stats, g_stats);
    cudaGetSymbolAddress((void**)&sacc,  g_statsacc);
    cudaGetSymbolAddress((void**)&M,     g_M);
    cudaGetSymbolAddress((void**)&Mv,    g_Mv);
    cudaGetSymbolAddress((void**)&bkq,   g_bkq);
    cudaGetSymbolAddress((void**)&u,     g_u);
    cudaGetSymbolAddress((void**)&bv2,   g_bv2);
    cudaGetSymbolAddress((void**)&beta,  g_beta);
    cudaGetSymbolAddress((void**)&corr,  g_corr);

    int natt5 = NLAG * NB * SS * VQ * VK;
    zero_kernel<<<(natt5 + 255) / 256, 256>>>(att5, natt5);
    zero_kernel<<<1, 256, 0>>>(sacc, 2 * CC * 2);

    // tiny weight precontractions
    precompute_kernel<<<132, 256>>>(Wq, bq, Wk, bk, Wv, bv, Wout,
                                    M, Mv, bkq, u, bv2, beta);

    // kq = M_s x_k + bkq  (replaces Wq AND Wk GEMMs; q, k tensors eliminated)
    gemm_tf32<<<dim3(COLS_K / 256, (SS * CC) / 64, NB), 256>>>(
        M, bkq, x_k, kq, CC, COLS_K, COLS_K, (long)CC * COLS_K, (long)SS * CC * COLS_K,
        CC, nullptr);
    // vw = Mv x_v + bv2  (replaces Wv GEMM + Wout precontraction; v tensor eliminated)
    gemm_tf32<<<dim3(COLS_K / 256, (SS * CC) / 64, NB), 256>>>(
        Mv, bv2, x_v, vw, CC, COLS_K, COLS_K, (long)CC * COLS_K, (long)SS * CC * COLS_K,
        CC, nullptr);
    // downsample projection (fused BN partial stats)
    gemm_tf32<<<dim3(COLS_T / 256, 1, NB), 256>>>(
        Wdown, bdown, x_q, db, CC, COLS_T, COLS_T, (long)CC * COLS_T, (long)CC * COLS_T,
        CC, sacc + 2 * CC);

    // q-bias cross term (fp32-exact)
    corr_kernel<<<NB * SS, 256>>>(x_k, u, beta, corr);

    // multi-lag scores (A = x_q directly) + softmax(+corr)
    scores_tf32<<<dim3(NB * SS, 16), 448>>>(x_q, kq, att5);
    softmax_kernel<<<NB * SS * VQ, 64>>>(att5, corr, att);

    // o1 = bout + vw (.) att  (fused BN partial stats)
    att_out_tf32<<<dim3((CC * TT) / 64, NB), 256>>>(att, vw, bout, o1, sacc);

    // finalize stats + fused epilogue
    finalize_stats<<<1, 2 * CC>>>(sacc, stats);
    long total4 = (long)NB * CC * COLS_T / 4;
    final_kernel<<<(unsigned)((total4 + 255) / 256), 256>>>(
        o1, db, stats, g_out, b_out, g_dn, b_dn, (float*)d_out);
}

// round 15
// speedup vs baseline: 1.8575x; 1.8575x over previous
#include <cuda_runtime.h>

#define NB 8
#define CC 64
#define TT 256
#define VQ 90
#define VK 50
#define SS 4
#define LAG 4
#define NLAG (LAG + 1)
#define TQ (TT - LAG)                 // 252
#define COLS_Q (TQ * VQ)              // 22680
#define COLS_T (TT * VQ)              // 23040
#define COLS_K (TT * VK)              // 12800
#define BN_EPS 1e-5f

// ---------------- tf32 mma helpers ----------------
__device__ __forceinline__ unsigned f2tf32(float x) {
    unsigned r;
    asm("cvt.rna.tf32.f32 %0, %1;" : "=r"(r) : "f"(x));
    return r;
}
__device__ __forceinline__ void mma_tf32(
    float& c0, float& c1, float& c2, float& c3,
    unsigned a0, unsigned a1, unsigned a2, unsigned a3,
    unsigned b0, unsigned b1)
{
    asm("mma.sync.aligned.m16n8k8.row.col.f32.tf32.tf32.f32 "
        "{%0,%1,%2,%3},{%4,%5,%6,%7},{%8,%9},{%0,%1,%2,%3};"
        : "+f"(c0), "+f"(c1), "+f"(c2), "+f"(c3)
        : "r"(a0), "r"(a1), "r"(a2), "r"(a3), "r"(b0), "r"(b1));
}

// ---------------- scratch (static device memory; no allocations) ----------------
__device__ float g_q   [NB * SS * CC * COLS_Q];
__device__ float g_k   [NB * SS * CC * COLS_K];
__device__ float g_vw  [NB * SS * CC * COLS_K];   // vw[n][s*64+co][t*VK+vk]
__device__ float g_o1  [NB * CC * COLS_T];
__device__ float g_d   [NB * CC * COLS_T];
__device__ float g_att5[NLAG * NB * SS * VQ * VK];
__device__ float g_att [NB * SS * VQ * VK];
__device__ float g_stats[2 * CC * 2];
__device__ float g_statsacc[2 * CC * 2];
__device__ float g_Mv  [SS * CC * CC];            // fused Wout_s Wv
__device__ float g_bv2 [SS * CC];                 // fused Wout_s bv

// ---------------- zero kernel ----------------
__global__ void zero_kernel(float* p, int n) {
    int i = blockIdx.x * blockDim.x + threadIdx.x;
    if (i < n) p[i] = 0.f;
}

// ---------------- tiny weight precontraction (fp32): Mv, bv2 ----------------
__global__ void precompute_mv(
    const float* __restrict__ Wv, const float* __restrict__ bv,
    const float* __restrict__ Wout,
    float* __restrict__ Mv, float* __restrict__ bv2)
{
    int idx = blockIdx.x * 256 + threadIdx.x;
    if (idx < 16384) {                 // Mv[(s,co)][c'']
        int sco = idx >> 6, cpp = idx & 63;
        int s = sco >> 6, co = sco & 63;
        float acc = 0.f;
        for (int c = 0; c < 64; c++)
            acc += Wout[co * 256 + (s << 6) + c] * Wv[c * 64 + cpp];
        Mv[idx] = acc;
    } else if (idx < 16640) {          // bv2[(s,co)]
        int j = idx - 16384; int s = j >> 6, co = j & 63;
        float acc = 0.f;
        for (int c = 0; c < 64; c++)
            acc += Wout[co * 256 + (s << 6) + c] * bv[c];
        bv2[j] = acc;
    }
}

// ---------------- conv1x1 GEMM via tf32 mma ----------------
// O[n][row0+r][col] = sum_k W[(row0+r)*lda + k] X[n][k][col] (+ bias[row])
// Block tile: 64 rows x 256 cols, K-chunk 32. 8 warps (2M x 4N), warp tile 32x64.
// statsAcc != nullptr: fused per-row (channel) sum/sumsq accumulation.
__global__ __launch_bounds__(256) void gemm_tf32(
    const float* __restrict__ W, const float* __restrict__ bias,
    const float* __restrict__ X, float* __restrict__ O,
    int K, int cols, int rsB, long bsB, long bsC, int lda,
    float* __restrict__ statsAcc)
{
    __shared__ __align__(16) unsigned char gsm[43008];
    unsigned (*Ws)[36]  = reinterpret_cast<unsigned (*)[36]>(gsm);
    unsigned (*Xs)[264] = reinterpret_cast<unsigned (*)[264]>(gsm + 9216);
    float    (*Cs)[260] = reinterpret_cast<float (*)[260]>(gsm);
    __shared__ float rsum[64], rsq[64];

    int tid = threadIdx.x;
    int lane = tid & 31;
    int w = tid >> 5;
    int wm = w & 1, wn = w >> 1;
    int lr = lane >> 2, lc = lane & 3;
    int n = blockIdx.z;
    int row0 = blockIdx.y * 64;
    int col0 = blockIdx.x * 256;
    const float* Xn = X + (long)n * bsB;
    float* On = O + (long)n * bsC;

    if (statsAcc && tid < 64) { rsum[tid] = 0.f; rsq[tid] = 0.f; }

    float acc[2][8][4];
#pragma unroll
    for (int mt = 0; mt < 2; mt++)
#pragma unroll
        for (int nt = 0; nt < 8; nt++)
#pragma unroll
            for (int e = 0; e < 4; e++) acc[mt][nt][e] = 0.f;

    for (int kc = 0; kc < K; kc += 32) {
        __syncthreads();
#pragma unroll
        for (int it = 0; it < 2; it++) {
            int idx = tid + it * 256;
            int r = idx >> 3, q4 = idx & 7;
            float4 wv = *reinterpret_cast<const float4*>(
                &W[(long)(row0 + r) * lda + kc + q4 * 4]);
            Ws[r][q4 * 4 + 0] = f2tf32(wv.x);
            Ws[r][q4 * 4 + 1] = f2tf32(wv.y);
            Ws[r][q4 * 4 + 2] = f2tf32(wv.z);
            Ws[r][q4 * 4 + 3] = f2tf32(wv.w);
        }
#pragma unroll
        for (int it = 0; it < 8; it++) {
            int idx = tid + it * 256;
            int kk = idx >> 6, c4 = idx & 63;
            int col = col0 + c4 * 4;
            float4 xv = make_float4(0.f, 0.f, 0.f, 0.f);
            if (col < cols)
                xv = *reinterpret_cast<const float4*>(&Xn[(long)(kc + kk) * rsB + col]);
            Xs[kk][c4 * 4 + 0] = f2tf32(xv.x);
            Xs[kk][c4 * 4 + 1] = f2tf32(xv.y);
            Xs[kk][c4 * 4 + 2] = f2tf32(xv.z);
            Xs[kk][c4 * 4 + 3] = f2tf32(xv.w);
        }
        __syncthreads();
#pragma unroll
        for (int kk = 0; kk < 32; kk += 8) {
            unsigned a[2][4];
#pragma unroll
            for (int mt = 0; mt < 2; mt++) {
                int m0 = wm * 32 + mt * 16;
                a[mt][0] = Ws[m0 + lr][kk + lc];
                a[mt][1] = Ws[m0 + 8 + lr][kk + lc];
                a[mt][2] = Ws[m0 + lr][kk + 4 + lc];
                a[mt][3] = Ws[m0 + 8 + lr][kk + 4 + lc];
            }
            unsigned b[8][2];
#pragma unroll
            for (int nt = 0; nt < 8; nt++) {
                int n0 = wn * 64 + nt * 8;
                b[nt][0] = Xs[kk + lc][n0 + lr];
                b[nt][1] = Xs[kk + 4 + lc][n0 + lr];
            }
#pragma unroll
            for (int mt = 0; mt < 2; mt++)
#pragma unroll
                for (int nt = 0; nt < 8; nt++)
                    mma_tf32(acc[mt][nt][0], acc[mt][nt][1], acc[mt][nt][2], acc[mt][nt][3],
                             a[mt][0], a[mt][1], a[mt][2], a[mt][3],
                             b[nt][0], b[nt][1]);
        }
    }
    for (int h = 0; h < 2; h++) {
        __syncthreads();
        if (wm == h) {
#pragma unroll
            for (int mt = 0; mt < 2; mt++) {
                int rloc = mt * 16 + lr;
                int r = row0 + h * 32 + rloc;
                float bv0 = bias ? bias[r] : 0.f;
                float bv8 = bias ? bias[r + 8] : 0.f;
#pragma unroll
                for (int nt = 0; nt < 8; nt++) {
                    int c = wn * 64 + nt * 8 + lc * 2;
                    Cs[rloc][c]         = acc[mt][nt][0] + bv0;
                    Cs[rloc][c + 1]     = acc[mt][nt][1] + bv0;
                    Cs[rloc + 8][c]     = acc[mt][nt][2] + bv8;
                    Cs[rloc + 8][c + 1] = acc[mt][nt][3] + bv8;
                }
            }
        }
        __syncthreads();
#pragma unroll
        for (int it = 0; it < 8; it++) {
            int idx = tid + it * 256;
            int rr = idx >> 6, c4 = idx & 63;
            int col = col0 + c4 * 4;
            if (col < cols) {
                float4 val = *reinterpret_cast<const float4*>(&Cs[rr][c4 * 4]);
                *reinterpret_cast<float4*>(
                    &On[(long)(row0 + h * 32 + rr) * cols + col]) = val;
            }
        }
        if (statsAcc) {
            int rr = tid & 31, seg = tid >> 5;
            float s = 0.f, q2 = 0.f;
#pragma unroll
            for (int j = 0; j < 32; j++) {
                int col = col0 + seg * 32 + j;
                if (col < cols) {
                    float xv = Cs[rr][seg * 32 + j];
                    s += xv; q2 += xv * xv;
                }
            }
            atomicAdd(&rsum[h * 32 + rr], s);
            atomicAdd(&rsq[h * 32 + rr], q2);
        }
    }
    if (statsAcc) {
        __syncthreads();
        if (tid < 64) {
            atomicAdd(&statsAcc[(row0 + tid) * 2 + 0], rsum[tid]);
            atomicAdd(&statsAcc[(row0 + tid) * 2 + 1], rsq[tid]);
        }
    }
}

// ---------------- 5-lag attention scores via tf32 mma, software-pipelined ----------------
#define SC_NQ 13                     // ceil(64*90 / 448)
#define SC_NK 8                      // ceil(68*50 / 448)
__global__ __launch_bounds__(448) void scores_tf32(
    const float* __restrict__ q, const float* __restrict__ k,
    float* __restrict__ att5)
{
    __shared__ unsigned q_s[64][104];  // [t][vq pad 90->104]
    __shared__ unsigned k_s[68][56];   // [t (+4 halo)][vk pad 50->56]
    int tid = threadIdx.x;
    int lane = tid & 31;
    int w = tid >> 5;                  // 0..13
    int wm = w & 1, wn = w >> 1;       // wn 0..6
    int lr = lane >> 2, lc = lane & 3;
    int ns = blockIdx.x;
    int n = ns >> 2, s = ns & 3;
    int c0 = blockIdx.y * 4;

    const float* qbase = q + (long)(n * SS * CC + s * CC + c0) * COLS_Q;
    const float* kbase = k + (long)(n * SS * CC + s * CC + c0) * COLS_K;

    int lagv[5], vkbv[5];
#pragma unroll
    for (int nt = 0; nt < 5; nt++) {
        int nn = wn * 40 + nt * 8;
        lagv[nt] = nn / 56;
        vkbv[nt] = nn % 56 + lr;
    }

    float acc[3][5][4];
#pragma unroll
    for (int mt = 0; mt < 3; mt++)
#pragma unroll
        for (int nt = 0; nt < 5; nt++)
#pragma unroll
            for (int e = 0; e < 4; e++) acc[mt][nt][e] = 0.f;

    for (int idx = tid; idx < 64 * 104; idx += 448) (&q_s[0][0])[idx] = 0u;
    for (int idx = tid; idx < 68 * 56; idx += 448) (&k_s[0][0])[idx] = 0u;

    float qv[SC_NQ], kv[SC_NK];
    {
        const float* qr = qbase;
        const float* kr = kbase;
#pragma unroll
        for (int i = 0; i < SC_NQ; i++) {
            int idx = tid + i * 448;
            qv[i] = (idx < 64 * VQ) ? qr[idx] : 0.f;
        }
#pragma unroll
        for (int i = 0; i < SC_NK; i++) {
            int idx = tid + i * 448;
            kv[i] = (idx < 68 * VK) ? kr[idx] : 0.f;
        }
    }
    __syncthreads();
#pragma unroll
    for (int i = 0; i < SC_NQ; i++) {
        int idx = tid + i * 448;
        if (idx < 64 * VQ) { int r = idx / VQ, c = idx - r * VQ; q_s[r][c] = f2tf32(qv[i]); }
    }
#pragma unroll
    for (int i = 0; i < SC_NK; i++) {
        int idx = tid + i * 448;
        if (idx < 68 * VK) { int r = idx / VK, c = idx - r * VK; k_s[r][c] = f2tf32(kv[i]); }
    }

#pragma unroll 1
    for (int chunk = 0; chunk < 16; chunk++) {
        __syncthreads();
        int nxt = chunk + 1;
        if (nxt < 16) {
            int cc = nxt >> 2, tch = nxt & 3;
            int t0 = tch * 64;
            const float* qr = qbase + (long)cc * COLS_Q + (long)t0 * VQ;
            int qlim = (TQ - t0) * VQ; if (qlim > 64 * VQ) qlim = 64 * VQ;
            const float* kr = kbase + (long)cc * COLS_K + (long)t0 * VK;
            int klim = (TT - t0) * VK; if (klim > 68 * VK) klim = 68 * VK;
#pragma unroll
            for (int i = 0; i < SC_NQ; i++) {
                int idx = tid + i * 448;
                qv[i] = (idx < qlim) ? qr[idx] : 0.f;
            }
#pragma unroll
            for (int i = 0; i < SC_NK; i++) {
                int idx = tid + i * 448;
                kv[i] = (idx < klim) ? kr[idx] : 0.f;
            }
        }
#pragma unroll
        for (int kk = 0; kk < 64; kk += 8) {
            unsigned a[3][4];
#pragma unroll
            for (int mt = 0; mt < 3; mt++) {
                int m0 = wm * 48 + mt * 16;
                a[mt][0] = q_s[kk + lc][m0 + lr];
                a[mt][1] = q_s[kk + lc][m0 + 8 + lr];
                a[mt][2] = q_s[kk + 4 + lc][m0 + lr];
                a[mt][3] = q_s[kk + 4 + lc][m0 + 8 + lr];
            }
            unsigned b[5][2];
#pragma unroll
            for (int nt = 0; nt < 5; nt++) {
                b[nt][0] = k_s[kk + lc + lagv[nt]][vkbv[nt]];
                b[nt][1] = k_s[kk + 4 + lc + lagv[nt]][vkbv[nt]];
            }
#pragma unroll
            for (int mt = 0; mt < 3; mt++)
#pragma unroll
                for (int nt = 0; nt < 5; nt++)
                    mma_tf32(acc[mt][nt][0], acc[mt][nt][1], acc[mt][nt][2], acc[mt][nt][3],
                             a[mt][0], a[mt][1], a[mt][2], a[mt][3],
                             b[nt][0], b[nt][1]);
        }
        __syncthreads();
        if (nxt < 16) {
#pragma unroll
            for (int i = 0; i < SC_NQ; i++) {
                int idx = tid + i * 448;
                if (idx < 64 * VQ) { int r = idx / VQ, c = idx - r * VQ; q_s[r][c] = f2tf32(qv[i]); }
            }
#pragma unroll
            for (int i = 0; i < SC_NK; i++) {
                int idx = tid + i * 448;
                if (idx < 68 * VK) { int r = idx / VK, c = idx - r * VK; k_s[r][c] = f2tf32(kv[i]); }
            }
        }
    }

#pragma unroll
    for (int mt = 0; mt < 3; mt++) {
        int vq = wm * 48 + mt * 16 + lr;
#pragma unroll
        for (int nt = 0; nt < 5; nt++) {
            int nn = wn * 40 + nt * 8 + lc * 2;
            int l = nn / 56;
            int vk = nn % 56;
            long base = (((long)(l * NB + n) * SS + s) * VQ);
            if (vq < VQ) {
                if (vk < VK)     atomicAdd(&att5[(base + vq) * VK + vk], acc[mt][nt][0]);
                if (vk + 1 < VK) atomicAdd(&att5[(base + vq) * VK + vk + 1], acc[mt][nt][1]);
            }
            if (vq + 8 < VQ) {
                if (vk < VK)     atomicAdd(&att5[(base + vq + 8) * VK + vk], acc[mt][nt][2]);
                if (vk + 1 < VK) atomicAdd(&att5[(base + vq + 8) * VK + vk + 1], acc[mt][nt][3]);
            }
        }
    }
}

// ---------------- (max+mean)/2 over lags, /scale, softmax over vk ----------------
__global__ void softmax_kernel(const float* __restrict__ att5, float* __restrict__ att)
{
    int r = blockIdx.x;               // 2880 rows
    int tid = threadIdx.x;            // 64
    __shared__ float red[64];
    const float halfInv = 0.5f / sqrtf((float)(CC * TQ));
    float p = -1e30f;
    if (tid < VK) {
        float mx = -1e30f, sm = 0.f;
#pragma unroll
        for (int l = 0; l < NLAG; l++) {
            float v = att5[((long)l * (NB * SS * VQ) + r) * VK + tid];
            mx = fmaxf(mx, v);
            sm += v;
        }
        p = (mx + sm * 0.2f) * halfInv;
    }
    red[tid] = p;
    __syncthreads();
    for (int o = 32; o > 0; o >>= 1) {
        if (tid < o) red[tid] = fmaxf(red[tid], red[tid + o]);
        __syncthreads();
    }
    float m = red[0];
    __syncthreads();
    float e = (tid < VK) ? expf(p - m) : 0.f;
    red[tid] = e;
    __syncthreads();
    for (int o = 32; o > 0; o >>= 1) {
        if (tid < o) red[tid] += red[tid + o];
        __syncthreads();
    }
    if (tid < VK) att[(long)r * VK + tid] = e / red[0];
}

// ---------------- o1[n,co,t,vq] = bout[co] + sum_{s,vk} vw[n,s,co,t,vk] * att[n,s,vq,vk] ----------------
__global__ __launch_bounds__(256) void att_out_tf32(
    const float* __restrict__ att, const float* __restrict__ vw,
    const float* __restrict__ bout, float* __restrict__ o1,
    float* __restrict__ statsAcc)
{
    __shared__ __align__(16) unsigned char ysm[38656];
    unsigned (*vt_s)[60]  = reinterpret_cast<unsigned (*)[60]>(ysm);
    unsigned (*at_s)[104] = reinterpret_cast<unsigned (*)[104]>(ysm + 15360);
    float    (*Cs)[96]    = reinterpret_cast<float (*)[96]>(ysm);
    __shared__ float r1[8], r2[8];

    int tid = threadIdx.x;
    int lane = tid & 31;
    int w = tid >> 5;
    int wm = w & 1, wn = w >> 1;
    int lr = lane >> 2, lc = lane & 3;
    int n = blockIdx.y;
    int ct0 = blockIdx.x * 64;
    int co = ct0 >> 8;
    int t0 = ct0 & 255;

    for (int idx = tid; idx < 64 * 60; idx += 256) (&vt_s[0][0])[idx] = 0u;
    for (int idx = tid; idx < 56 * 104; idx += 256) (&at_s[0][0])[idx] = 0u;

    float acc[2][3][4];
#pragma unroll
    for (int mt = 0; mt < 2; mt++)
#pragma unroll
        for (int nt = 0; nt < 3; nt++)
#pragma unroll
            for (int e = 0; e < 4; e++) acc[mt][nt][e] = 0.f;

#pragma unroll 1
    for (int s = 0; s < SS; s++) {
        __syncthreads();
        const float* ab = att + (long)(n * SS + s) * (VQ * VK);
        for (int idx = tid; idx < VQ * VK; idx += 256) {
            int vq = idx / VK, vk = idx - vq * VK;
            at_s[vk][vq] = f2tf32(ab[idx]);
        }
        const float* vb = vw + ((long)(n * SS + s) * CC + co) * COLS_K + (long)t0 * VK;
        for (int idx = tid; idx < 64 * VK; idx += 256) {
            int r = idx / VK, c = idx - r * VK;
            vt_s[r][c] = f2tf32(vb[idx]);
        }
        __syncthreads();
#pragma unroll
        for (int kk = 0; kk < 56; kk += 8) {
            unsigned a[2][4];
#pragma unroll
            for (int mt = 0; mt < 2; mt++) {
                int m0 = wm * 32 + mt * 16;
                a[mt][0] = vt_s[m0 + lr][kk + lc];
                a[mt][1] = vt_s[m0 + 8 + lr][kk + lc];
                a[mt][2] = vt_s[m0 + lr][kk + 4 + lc];
                a[mt][3] = vt_s[m0 + 8 + lr][kk + 4 + lc];
            }
            unsigned b[3][2];
#pragma unroll
            for (int nt = 0; nt < 3; nt++) {
                int n0 = wn * 24 + nt * 8;
                b[nt][0] = at_s[kk + lc][n0 + lr];
                b[nt][1] = at_s[kk + 4 + lc][n0 + lr];
            }
#pragma unroll
            for (int mt = 0; mt < 2; mt++)
#pragma unroll
                for (int nt = 0; nt < 3; nt++)
                    mma_tf32(acc[mt][nt][0], acc[mt][nt][1], acc[mt][nt][2], acc[mt][nt][3],
                             a[mt][0], a[mt][1], a[mt][2], a[mt][3],
                             b[nt][0], b[nt][1]);
        }
    }

    __syncthreads();
    float bv = bout[co];
#pragma unroll
    for (int mt = 0; mt < 2; mt++) {
        int rloc = wm * 32 + mt * 16 + lr;
#pragma unroll
        for (int nt = 0; nt < 3; nt++) {
            int c = wn * 24 + nt * 8 + lc * 2;
            Cs[rloc][c]         = acc[mt][nt][0] + bv;
            Cs[rloc][c + 1]     = acc[mt][nt][1] + bv;
            Cs[rloc + 8][c]     = acc[mt][nt][2] + bv;
            Cs[rloc + 8][c + 1] = acc[mt][nt][3] + bv;
        }
    }
    __syncthreads();
    long obase = (long)n * CC * COLS_T + (long)ct0 * VQ;
    float s1 = 0.f, s2 = 0.f;
#pragma unroll
    for (int it = 0; it < 12; it++) {
        int idx = tid + it * 256;
        if (idx < 64 * 45) {
            int r = idx / 45, c2 = idx - r * 45;
            float2 val = *reinterpret_cast<const float2*>(&Cs[r][c2 * 2]);
            *reinterpret_cast<float2*>(&o1[obase + (long)r * VQ + c2 * 2]) = val;
            s1 += val.x + val.y;
            s2 += val.x * val.x + val.y * val.y;
        }
    }
#pragma unroll
    for (int o = 16; o > 0; o >>= 1) {
        s1 += __shfl_down_sync(0xffffffff, s1, o);
        s2 += __shfl_down_sync(0xffffffff, s2, o);
    }
    if (lane == 0) { r1[w] = s1; r2[w] = s2; }
    __syncthreads();
    if (tid == 0) {
        float t1 = 0.f, t2 = 0.f;
#pragma unroll
        for (int i = 0; i < 8; i++) { t1 += r1[i]; t2 += r2[i]; }
        atomicAdd(&statsAcc[co * 2 + 0], t1);
        atomicAdd(&statsAcc[co * 2 + 1], t2);
    }
}

// ---------------- finalize BN stats from fused accumulators ----------------
__global__ void finalize_stats(const float* __restrict__ acc, float* __restrict__ stats)
{
    int i = threadIdx.x;              // 128 = which*64+co
    float M = (float)NB * COLS_T;
    float mean = acc[i * 2 + 0] / M;
    float var = acc[i * 2 + 1] / M - mean * mean;
    stats[i * 2 + 0] = mean;
    stats[i * 2 + 1] = rsqrtf(var + BN_EPS);
}

// ---------------- BN both paths + add + leaky relu (vectorized) ----------------
__global__ void final_kernel(const float* __restrict__ o1, const float* __restrict__ d,
                             const float* __restrict__ stats,
                             const float* __restrict__ gout, const float* __restrict__ bout,
                             const float* __restrict__ gdown, const float* __restrict__ bdown,
                             float* __restrict__ out)
{
    long i4 = (long)blockIdx.x * blockDim.x + threadIdx.x;
    long total4 = (long)NB * CC * COLS_T / 4;
    if (i4 >= total4) return;
    long idx = i4 * 4;
    int co = (int)((idx / COLS_T) % CC);
    float mo = stats[co * 2 + 0], iso = stats[co * 2 + 1];
    float md = stats[(CC + co) * 2 + 0], isd = stats[(CC + co) * 2 + 1];
    float so = iso * gout[co], sd = isd * gdown[co];
    float bo = bout[co] - mo * so, bd = bdown[co] - md * sd;
    float4 a = *reinterpret_cast<const float4*>(&o1[idx]);
    float4 b = *reinterpret_cast<const float4*>(&d[idx]);
    float4 r;
    float v;
    v = a.x * so + bo + b.x * sd + bd; r.x = v > 0.f ? v : 0.1f * v;
    v = a.y * so + bo + b.y * sd + bd; r.y = v > 0.f ? v : 0.1f * v;
    v = a.z * so + bo + b.z * sd + bd; r.z = v > 0.f ? v : 0.1f * v;
    v = a.w * so + bo + b.w * sd + bd; r.w = v > 0.f ? v : 0.1f * v;
    *reinterpret_cast<float4*>(&out[idx]) = r;
}

// ---------------- launch ----------------
extern "C" void kernel_launch(void* const* d_in, const int* in_sizes, int n_in,
                              void* d_out, int out_size)
{
    const float* x_q   = (const float*)d_in[0];
    const float* x_k   = (const float*)d_in[1];
    const float* x_v   = (const float*)d_in[2];
    const float* Wq    = (const float*)d_in[3];
    const float* bq    = (const float*)d_in[4];
    const float* Wk    = (const float*)d_in[5];
    const float* bk    = (const float*)d_in[6];
    const float* Wv    = (const float*)d_in[7];
    const float* bv    = (const float*)d_in[8];
    const float* Wout  = (const float*)d_in[9];
    const float* bout  = (const float*)d_in[10];
    const float* g_out = (const float*)d_in[11];
    const float* b_out = (const float*)d_in[12];
    const float* Wdown = (const float*)d_in[13];
    const float* bdown = (const float*)d_in[14];
    const float* g_dn  = (const float*)d_in[15];
    const float* b_dn  = (const float*)d_in[16];

    float *q, *k, *vw, *o1, *db, *att5, *att, *stats, *sacc, *Mv, *bv2;
    cudaGetSymbolAddress((void**)&q,     g_q);
    cudaGetSymbolAddress((void**)&k,     g_k);
    cudaGetSymbolAddress((void**)&vw,    g_vw);
    cudaGetSymbolAddress((void**)&o1,    g_o1);
    cudaGetSymbolAddress((void**)&db,    g_d);
    cudaGetSymbolAddress((void**)&att5,  g_att5);
    cudaGetSymbolAddress((void**)&att,   g_att);
    cudaGetSymbolAddress((void**)&stats, g_stats);
    cudaGetSymbolAddress((void**)&sacc,  g_statsacc);
    cudaGetSymbolAddress((void**)&Mv,    g_Mv);
    cudaGetSymbolAddress((void**)&bv2,   g_bv2);

    int natt5 = NLAG * NB * SS * VQ * VK;
    zero_kernel<<<(natt5 + 255) / 256, 256>>>(att5, natt5);
    zero_kernel<<<1, 256, 0>>>(sacc, 2 * CC * 2);

    // tiny precontraction: Mv = Wout_s Wv, bv2 = Wout_s bv
    precompute_mv<<<65, 256>>>(Wv, bv, Wout, Mv, bv2);

    // projections (tf32 mma) — champion R11 structure
    gemm_tf32<<<dim3((COLS_Q + 255) / 256, (SS * CC) / 64, NB), 256>>>(
        Wq, bq, x_q, q, CC, COLS_Q, COLS_T, (long)CC * COLS_T, (long)SS * CC * COLS_Q,
        CC, nullptr);
    gemm_tf32<<<dim3(COLS_K / 256, (SS * CC) / 64, NB), 256>>>(
        Wk, bk, x_k, k, CC, COLS_K, COLS_K, (long)CC * COLS_K, (long)SS * CC * COLS_K,
        CC, nullptr);
    // vw = Mv x_v + bv2  (replaces Wv GEMM + Wout-slab GEMM; v tensor eliminated)
    gemm_tf32<<<dim3(COLS_K / 256, (SS * CC) / 64, NB), 256>>>(
        Mv, bv2, x_v, vw, CC, COLS_K, COLS_K, (long)CC * COLS_K, (long)SS * CC * COLS_K,
        CC, nullptr);
    // downsample projection (fused BN partial stats)
    gemm_tf32<<<dim3(COLS_T / 256, 1, NB), 256>>>(
        Wdown, bdown, x_q, db, CC, COLS_T, COLS_T, (long)CC * COLS_T, (long)CC * COLS_T,
        CC, sacc + 2 * CC);

    // multi-lag scores (tf32 mma, pipelined) + softmax
    scores_tf32<<<dim3(NB * SS, 16), 448>>>(q, k, att5);
    softmax_kernel<<<NB * SS * VQ, 64>>>(att5, att);

    // o1 = bout + vw (.) att  (fused BN partial stats)
    att_out_tf32<<<dim3((CC * TT) / 64, NB), 256>>>(att, vw, bout, o1, sacc);

    // finalize stats + fused epilogue
    finalize_stats<<<1, 2 * CC>>>(sacc, stats);
    long total4 = (long)NB * CC * COLS_T / 4;
    final_kernel<<<(unsigned)((total4 + 255) / 256), 256>>>(
        o1, db, stats, g_out, b_out, g_dn, b_dn, (float*)d_out);
}